// round 14
// baseline (speedup 1.0000x reference)
#include <cuda_runtime.h>

#define BB 64
#define SS 512
#define HH 768
#define TTAG 17
#define TPOS 45
#define MM (BB*SS)
#define MAXT 45

// ---- scratch (no allocations allowed) ----
__device__ float g_tag[MM*TTAG];
__device__ float g_pos[MM*TPOS];
__device__ float g_Etag[MM*TTAG];   // exp(e_j - e_0)
__device__ float g_Epos[MM*TPOS];
__device__ float g_diff[2*BB];
__device__ int   g_cnt;             // zero-init; reset by finalizing block

// ---- packed f32x2 helpers ----
__device__ __forceinline__ void fma2(unsigned long long& d,
                                     unsigned long long a, unsigned long long b) {
    asm("fma.rn.f32x2 %0, %1, %2, %3;" : "=l"(d) : "l"(a), "l"(b), "l"(d));
}
__device__ __forceinline__ unsigned long long add2(unsigned long long a, unsigned long long b) {
    unsigned long long d;
    asm("add.rn.f32x2 %0, %1, %2;" : "=l"(d) : "l"(a), "l"(b));
    return d;
}
__device__ __forceinline__ unsigned long long pack2(float lo, float hi) {
    unsigned long long d;
    asm("mov.b64 %0, {%1, %2};" : "=l"(d)
        : "r"(__float_as_uint(lo)), "r"(__float_as_uint(hi)));
    return d;
}
__device__ __forceinline__ void unpack2(unsigned long long v, float& lo, float& hi) {
    unsigned a, b;
    asm("mov.b64 {%0, %1}, %2;" : "=r"(a), "=r"(b) : "l"(v));
    lo = __uint_as_float(a); hi = __uint_as_float(b);
}

// ============================================================
// GEMM + fused E precompute (validated; ~100us)
// ============================================================
__global__ __launch_bounds__(256, 2) void gemm_kernel(
    const float* __restrict__ hidden,
    const float* __restrict__ Wt, const float* __restrict__ bt,
    const float* __restrict__ Wp, const float* __restrict__ bp)
{
    __shared__ float Hs[128*36];
    __shared__ float Ws[32*64];
    __shared__ float e0t[128], e0p[128];
    const int tid = threadIdx.x;
    const int ty = tid >> 4, tx = tid & 15;
    const int tok0 = blockIdx.x * 128;

    float acc[8][4];
#pragma unroll
    for (int i = 0; i < 8; i++)
#pragma unroll
        for (int j = 0; j < 4; j++) acc[i][j] = 0.f;

    float4 hreg[4];
    float  wreg[8];
    {
#pragma unroll
        for (int i = 0; i < 4; i++) {
            int idx = tid + i*256;
            int r = idx >> 3, c4 = idx & 7;
            hreg[i] = *reinterpret_cast<const float4*>(
                hidden + (size_t)(tok0 + r)*HH + c4*4);
        }
#pragma unroll
        for (int i = 0; i < 8; i++) {
            int idx = tid + i*256;
            int kk = idx >> 6, c = idx & 63;
            float v = 0.f;
            if (c < TTAG)    v = Wt[kk*TTAG + c];
            else if (c < 62) v = Wp[kk*TPOS + (c - TTAG)];
            wreg[i] = v;
        }
    }
    for (int ch = 0; ch < HH/32; ch++) {
#pragma unroll
        for (int i = 0; i < 4; i++) {
            int idx = tid + i*256;
            int r = idx >> 3, c4 = idx & 7;
            *reinterpret_cast<float4*>(&Hs[r*36 + c4*4]) = hreg[i];
        }
#pragma unroll
        for (int i = 0; i < 8; i++) Ws[tid + i*256] = wreg[i];
        __syncthreads();
        if (ch + 1 < HH/32) {
            const int k0 = (ch+1)*32;
#pragma unroll
            for (int i = 0; i < 4; i++) {
                int idx = tid + i*256;
                int r = idx >> 3, c4 = idx & 7;
                hreg[i] = *reinterpret_cast<const float4*>(
                    hidden + (size_t)(tok0 + r)*HH + k0 + c4*4);
            }
#pragma unroll
            for (int i = 0; i < 8; i++) {
                int idx = tid + i*256;
                int kk = idx >> 6, c = idx & 63;
                float v = 0.f;
                if (c < TTAG)    v = Wt[(k0+kk)*TTAG + c];
                else if (c < 62) v = Wp[(k0+kk)*TPOS + (c - TTAG)];
                wreg[i] = v;
            }
        }
#pragma unroll
        for (int kk = 0; kk < 32; kk++) {
            float4 bv = *reinterpret_cast<float4*>(&Ws[kk*64 + tx*4]);
#pragma unroll
            for (int i = 0; i < 8; i++) {
                float a = Hs[(ty*8+i)*36 + kk];
                acc[i][0] = fmaf(a, bv.x, acc[i][0]);
                acc[i][1] = fmaf(a, bv.y, acc[i][1]);
                acc[i][2] = fmaf(a, bv.z, acc[i][2]);
                acc[i][3] = fmaf(a, bv.w, acc[i][3]);
            }
        }
        __syncthreads();
    }
#pragma unroll
    for (int i = 0; i < 8; i++) {
        if (tx == 0) e0t[ty*8+i] = acc[i][0] + bt[0];
        if (tx == 4) e0p[ty*8+i] = acc[i][1] + bp[0];
    }
    __syncthreads();
#pragma unroll
    for (int i = 0; i < 8; i++) {
        int rl = ty*8 + i;
        int r = tok0 + rl;
#pragma unroll
        for (int j = 0; j < 4; j++) {
            int c = tx*4 + j;
            if (c < TTAG) {
                float v = acc[i][j] + bt[c];
                g_tag [(size_t)r*TTAG + c] = v;
                g_Etag[(size_t)r*TTAG + c] = __expf(v - e0t[rl]);
            } else if (c < 62) {
                int cp = c - TTAG;
                float v = acc[i][j] + bp[cp];
                g_pos [(size_t)r*TPOS + cp] = v;
                g_Epos[(size_t)r*TPOS + cp] = __expf(v - e0p[rl]);
            }
        }
    }
}

// ============================================================
// CRF: one block per (head,batch). 160 threads:
//   warp 0:  self-contained forward (syncwarp loop, rescale every 8 steps)
//   warps 1-3: Viterbi (2 lanes/col; FMNMX-tree max + ffs-bitmask argmin index)
//   warp 4:  one-shot numerator + masked-e0 sum
// ============================================================
struct __align__(16) CrfSmem {
    float a2[2][96];       // duplicated pairs (a_i,a_i)
    float sv[2][48];
    unsigned mword[16];
    float num_sh, den_sh, e0sum;
    unsigned char hist[(SS-1)*MAXT];
    unsigned char path[SS];
};

template<int T>
__device__ __forceinline__ void crf_chain(
    CrfSmem& s,
    const float* __restrict__ stg, const float* __restrict__ trg,
    const float* __restrict__ eng,
    const int* __restrict__ tgt, const int* __restrict__ mask,
    const float* __restrict__ eb, const float* __restrict__ Eb, int b)
{
    const int tid = threadIdx.x;
    const int w = tid >> 5, lane = tid & 31;
    constexpr int SHC = (T + 1) / 2;
    constexpr int BASE_B = (T/2) & ~3;
    constexpr int CA = T - BASE_B;
    constexpr int BIG = 1 << 20;

    // ---- init ----
    if (tid < 16) {
        unsigned bits = 0;
#pragma unroll
        for (int k = 0; k < 32; k++)
            bits |= (mask[b*SS + tid*32 + k] != 0 ? 1u : 0u) << k;
        s.mword[tid] = bits;
    }
    if (w == 0 && lane < SHC) {
        int j0 = lane, j1 = (lane + SHC < T) ? lane + SHC : lane;
        float r0 = stg[0] + eb[0];
        float a0 = __expf(stg[j0] + eb[j0] - r0);
        float a1 = __expf(stg[j1] + eb[j1] - r0);
        *(unsigned long long*)&s.a2[0][2*j0] = pack2(a0, a0);
        *(unsigned long long*)&s.a2[0][2*j1] = pack2(a1, a1);
    }
    if (w >= 1 && w <= 3) {
        int vl = tid - 32, col = vl >> 1;
        if (col < T && !(vl & 1)) s.sv[0][col] = stg[col] + eb[col];
    }
    __syncthreads();

    if (w == 0) {
        // ============ forward warp: fully self-contained ============
        const bool act = lane < SHC;
        const int j0 = act ? lane : 0;
        const bool j1ok = act && (lane + SHC < T);
        const int j1 = j1ok ? lane + SHC : j0;
        const float wm0 = act ? 1.f : 0.f;
        const float wm1 = j1ok ? 1.f : 0.f;
        unsigned long long tc2[T];
#pragma unroll
        for (int i = 0; i < T; i++)
            tc2[i] = pack2(__expf(trg[i*T + j0]), __expf(trg[i*T + j1]));
        const float ref0 = stg[0] + eb[0];
        float acur0 = __expf(stg[j0] + eb[j0] - ref0);
        float acur1 = __expf(stg[j1] + eb[j1] - ref0);
        float E0n = Eb[T + j0], E1n = Eb[T + j1];
        float Lr = 0.f;

        for (int t = 1; t < SS; t++) {
            const int pb = (t-1) & 1, cb = t & 1;
            unsigned mt = (s.mword[t >> 5] >> (t & 31)) & 1u;
            float E0 = E0n, E1 = E1n;
            if (t + 1 < SS) { E0n = Eb[(size_t)(t+1)*T + j0]; E1n = Eb[(size_t)(t+1)*T + j1]; }

            unsigned long long d[4] = {0ull, 0ull, 0ull, 0ull};
            const float* ap = s.a2[pb];
#pragma unroll
            for (int k = 0; k < T/2; k++) {
                ulonglong2 q = *(const ulonglong2*)(ap + 4*k);
                fma2(d[(2*k) & 3],   q.x, tc2[2*k]);
                fma2(d[(2*k+1) & 3], q.y, tc2[2*k+1]);
            }
            if (T & 1) {
                unsigned long long qa = *(const unsigned long long*)(ap + 2*(T-1));
                fma2(d[(T-1) & 3], qa, tc2[T-1]);
            }
            unsigned long long dd = add2(add2(d[0], d[1]), add2(d[2], d[3]));
            float dot0, dot1; unpack2(dd, dot0, dot1);
            float v0 = mt ? dot0 * E0 : acur0;
            float v1 = mt ? dot1 * E1 : acur1;
            if ((t & 7) == 0) {
                // amortized rescale: uniform factor, exactly compensated in Lr
                float ssum = fmaf(v1, wm1, v0 * wm0);
#pragma unroll
                for (int o = 16; o > 0; o >>= 1)
                    ssum += __shfl_xor_sync(0xffffffffu, ssum, o);
                float iv = 1.f / ssum;
                Lr += __logf(ssum);
                v0 *= iv; v1 *= iv;
            }
            acur0 = v0; acur1 = v1;
            if (act) {
                *(unsigned long long*)&s.a2[cb][2*j0] = pack2(v0, v0);
                *(unsigned long long*)&s.a2[cb][2*j1] = pack2(v1, v1);
            }
            __syncwarp();
        }
        if (lane == 0) {
            float sm = 0.f;
#pragma unroll
            for (int i = 0; i < T; i++) sm += s.a2[1][2*i] * __expf(eng[i]);
            s.den_sh = ref0 + Lr + __logf(sm);   // + e0sum added at combine
        }
    } else if (w == 4) {
        // ============ one-shot: numerator + masked-e0 sum ============
        float pacc = 0.f, esum = 0.f; int mxt = 0;
        for (int t = lane; t < SS; t += 32) {
            int tg = tgt[b*SS + t];
            if (t == 0) {
                pacc += stg[tg] + eb[tg];
            } else if (mask[b*SS + t] > 0) {
                int tgp = tgt[b*SS + t - 1];
                pacc += trg[tgp*T + tg] + eb[(size_t)t*T + tg];
                esum += eb[(size_t)t*T];
                mxt = max(mxt, t);
            }
        }
#pragma unroll
        for (int o = 16; o > 0; o >>= 1) {
            pacc += __shfl_xor_sync(0xffffffffu, pacc, o);
            esum += __shfl_xor_sync(0xffffffffu, esum, o);
            mxt = max(mxt, __shfl_xor_sync(0xffffffffu, mxt, o));
        }
        if (lane == 0) {
            s.num_sh = pacc + eng[tgt[b*SS + mxt]];
            s.e0sum = esum;
        }
    } else {
        // ===== viterbi warps (1-3): FMNMX-tree max + ffs-bitmask index =====
        const int vl = tid - 32;
        const int col = vl >> 1;
        const bool act = col < T;
        const bool isA = !(vl & 1);
        const int jj = act ? col : 0;
        const int base = isA ? 0 : BASE_B;
        float tc[CA];
#pragma unroll
        for (int k = 0; k < CA; k++) tc[k] = trg[(base + k)*T + jj];
        float svprev = stg[jj] + eb[jj];
        float evq1 = eb[T + jj];                         // e[1]
        float evq2 = (2 < SS) ? eb[2*T + jj] : 0.f;      // e[2]

        for (int t = 1; t < SS; t++) {
            const int pb = (t-1) & 1, cb = t & 1;
            float ev = evq1; evq1 = evq2;                // distance-2 prefetch
            if (t + 2 < SS) evq2 = eb[(size_t)(t+2)*T + jj];

            float cand[CA];
            const float* sp = s.sv[pb] + base;
            constexpr int C4 = CA / 4;
#pragma unroll
            for (int k = 0; k < C4; k++) {
                float4 q = *(const float4*)(sp + 4*k);
                cand[4*k+0] = q.x + tc[4*k+0];
                cand[4*k+1] = q.y + tc[4*k+1];
                cand[4*k+2] = q.z + tc[4*k+2];
                cand[4*k+3] = q.w + tc[4*k+3];
            }
#pragma unroll
            for (int r = 4*C4; r < CA; r++) cand[r] = sp[r] + tc[r];

            // value max: 4-accumulator FMNMX trees (4-cyc ops, no predicates)
            float mx0 = cand[0];
            float mx1 = (CA > 1) ? cand[1] : cand[0];
            float mx2 = (CA > 2) ? cand[2] : cand[0];
            float mx3 = (CA > 3) ? cand[3] : cand[0];
#pragma unroll
            for (int k = 4; k < CA; k++) {
                if ((k & 3) == 0) mx0 = fmaxf(mx0, cand[k]);
                else if ((k & 3) == 1) mx1 = fmaxf(mx1, cand[k]);
                else if ((k & 3) == 2) mx2 = fmaxf(mx2, cand[k]);
                else mx3 = fmaxf(mx3, cand[k]);
            }
            float best = fmaxf(fmaxf(mx0, mx1), fmaxf(mx2, mx3));
            // lowest index: equality bitmask (pred-as-data) + ffs
            unsigned msk = 0u;
#pragma unroll
            for (int k = 0; k < CA; k++)
                msk |= (cand[k] == best) ? (1u << k) : 0u;
            int arg = base + (__ffs(msk) - 1);   // msk != 0: fmax returns an operand
            // merge with partner lane (min global index on value ties)
            float bo = __shfl_xor_sync(0xffffffffu, best, 1);
            int   io = __shfl_xor_sync(0xffffffffu, arg, 1);
            float bm = fmaxf(best, bo);
            int ia = (best == bm) ? arg : BIG;
            int ib = (bo == bm) ? io : BIG;
            int argm = min(ia, ib);

            if (isA && act) {
                unsigned mt = (s.mword[t >> 5] >> (t & 31)) & 1u;
                float svnew; int h;
                if (mt) { svnew = bm + ev; h = argm; }
                else    { svnew = svprev;  h = col; }
                s.sv[cb][col] = svnew;
                svprev = svnew;
                s.hist[(t-1)*T + col] = (unsigned char)h;
            }
            asm volatile("bar.sync 2, 96;" ::: "memory");
        }
        // backtrace (warp 1, lane 0)
        if (tid == 32) {
            float bv = -1e30f; int cur = 0;
#pragma unroll
            for (int j = 0; j < T; j++) {
                float c = s.sv[1][j] + eng[j];
                if (c > bv) { bv = c; cur = j; }
            }
            s.path[SS-1] = (unsigned char)cur;
            for (int tt = SS-1; tt >= 1; tt--) {
                cur = s.hist[(tt-1)*T + cur];
                s.path[tt-1] = (unsigned char)cur;
            }
        }
    }
}

__global__ __launch_bounds__(160) void crf_kernel(
    const float* __restrict__ st_t, const float* __restrict__ tr_t, const float* __restrict__ en_t,
    const float* __restrict__ st_p, const float* __restrict__ tr_p, const float* __restrict__ en_p,
    const int* __restrict__ tgt_t, const int* __restrict__ tgt_p,
    const int* __restrict__ mask,
    float* __restrict__ out, int out_size)
{
    __shared__ CrfSmem s;
    const int head = blockIdx.x >> 6;
    const int b    = blockIdx.x & 63;
    float* pred = out + (size_t)head*MM + (size_t)b*SS;
    if (head == 0)
        crf_chain<TTAG>(s, st_t, tr_t, en_t, tgt_t, mask,
                        g_tag  + (size_t)b*SS*TTAG,
                        g_Etag + (size_t)b*SS*TTAG, b);
    else
        crf_chain<TPOS>(s, st_p, tr_p, en_p, tgt_p, mask,
                        g_pos  + (size_t)b*SS*TPOS,
                        g_Epos + (size_t)b*SS*TPOS, b);
    __syncthreads();
    // coalesced path write (warp 0 now free)
    if (threadIdx.x < 32)
        for (int i = threadIdx.x; i < SS; i += 32) pred[i] = (float)s.path[i];
    // fused finalize: last block sums all diffs
    if (threadIdx.x == 0) {
        g_diff[head*BB + b] = s.num_sh - (s.den_sh + s.e0sum);
        __threadfence();
        int old = atomicAdd(&g_cnt, 1);
        if (old == 2*BB - 1) {
            __threadfence();
            float s0 = 0.f, s1 = 0.f;
            for (int i = 0; i < BB; i++) { s0 += g_diff[i]; s1 += g_diff[BB + i]; }
            if (out_size > 2*MM)     out[2*MM]     = -s0 / (float)BB;
            if (out_size > 2*MM + 1) out[2*MM + 1] = -s1 / (float)BB;
            g_cnt = 0;   // reset for next graph replay
        }
    }
}

extern "C" void kernel_launch(void* const* d_in, const int* in_sizes, int n_in,
                              void* d_out, int out_size)
{
    const float* hidden = (const float*)d_in[0];
    const int*   mask   = (const int*)d_in[1];
    const int*   tgt_t  = (const int*)d_in[2];
    const int*   tgt_p  = (const int*)d_in[3];
    const float* Wt     = (const float*)d_in[4];
    const float* bt     = (const float*)d_in[5];
    const float* Wp     = (const float*)d_in[6];
    const float* bp     = (const float*)d_in[7];
    const float* st_t   = (const float*)d_in[8];
    const float* tr_t   = (const float*)d_in[9];
    const float* en_t   = (const float*)d_in[10];
    const float* st_p   = (const float*)d_in[11];
    const float* tr_p   = (const float*)d_in[12];
    const float* en_p   = (const float*)d_in[13];
    float* out = (float*)d_out;

    gemm_kernel<<<MM/128, 256>>>(hidden, Wt, bt, Wp, bp);
    crf_kernel<<<2*BB, 160>>>(st_t, tr_t, en_t, st_p, tr_p, en_p,
                              tgt_t, tgt_p, mask, out, out_size);
}

// round 15
// speedup vs baseline: 1.0266x; 1.0266x over previous
#include <cuda_runtime.h>

#define BB 64
#define SS 512
#define HH 768
#define TTAG 17
#define TPOS 45
#define MM (BB*SS)
#define MAXT 45

// ---- scratch (no allocations allowed) ----
__device__ float g_tag[MM*TTAG];
__device__ float g_pos[MM*TPOS];
__device__ float g_Etag[MM*TTAG];   // exp(e_j - e_0)
__device__ float g_Epos[MM*TPOS];
__device__ float g_diff[2*BB];
__device__ int   g_cnt;             // zero-init; reset by finalizing block

// ---- packed f32x2 helpers ----
__device__ __forceinline__ void fma2(unsigned long long& d,
                                     unsigned long long a, unsigned long long b) {
    asm("fma.rn.f32x2 %0, %1, %2, %3;" : "=l"(d) : "l"(a), "l"(b), "l"(d));
}
__device__ __forceinline__ unsigned long long add2(unsigned long long a, unsigned long long b) {
    unsigned long long d;
    asm("add.rn.f32x2 %0, %1, %2;" : "=l"(d) : "l"(a), "l"(b));
    return d;
}
__device__ __forceinline__ unsigned long long pack2(float lo, float hi) {
    unsigned long long d;
    asm("mov.b64 %0, {%1, %2};" : "=l"(d)
        : "r"(__float_as_uint(lo)), "r"(__float_as_uint(hi)));
    return d;
}
__device__ __forceinline__ void unpack2(unsigned long long v, float& lo, float& hi) {
    unsigned a, b;
    asm("mov.b64 {%0, %1}, %2;" : "=r"(a), "=r"(b) : "l"(v));
    lo = __uint_as_float(a); hi = __uint_as_float(b);
}

// ============================================================
// GEMM + fused E precompute (validated; ~100us)
// ============================================================
__global__ __launch_bounds__(256, 2) void gemm_kernel(
    const float* __restrict__ hidden,
    const float* __restrict__ Wt, const float* __restrict__ bt,
    const float* __restrict__ Wp, const float* __restrict__ bp)
{
    __shared__ float Hs[128*36];
    __shared__ float Ws[32*64];
    __shared__ float e0t[128], e0p[128];
    const int tid = threadIdx.x;
    const int ty = tid >> 4, tx = tid & 15;
    const int tok0 = blockIdx.x * 128;

    float acc[8][4];
#pragma unroll
    for (int i = 0; i < 8; i++)
#pragma unroll
        for (int j = 0; j < 4; j++) acc[i][j] = 0.f;

    float4 hreg[4];
    float  wreg[8];
    {
#pragma unroll
        for (int i = 0; i < 4; i++) {
            int idx = tid + i*256;
            int r = idx >> 3, c4 = idx & 7;
            hreg[i] = *reinterpret_cast<const float4*>(
                hidden + (size_t)(tok0 + r)*HH + c4*4);
        }
#pragma unroll
        for (int i = 0; i < 8; i++) {
            int idx = tid + i*256;
            int kk = idx >> 6, c = idx & 63;
            float v = 0.f;
            if (c < TTAG)    v = Wt[kk*TTAG + c];
            else if (c < 62) v = Wp[kk*TPOS + (c - TTAG)];
            wreg[i] = v;
        }
    }
    for (int ch = 0; ch < HH/32; ch++) {
#pragma unroll
        for (int i = 0; i < 4; i++) {
            int idx = tid + i*256;
            int r = idx >> 3, c4 = idx & 7;
            *reinterpret_cast<float4*>(&Hs[r*36 + c4*4]) = hreg[i];
        }
#pragma unroll
        for (int i = 0; i < 8; i++) Ws[tid + i*256] = wreg[i];
        __syncthreads();
        if (ch + 1 < HH/32) {
            const int k0 = (ch+1)*32;
#pragma unroll
            for (int i = 0; i < 4; i++) {
                int idx = tid + i*256;
                int r = idx >> 3, c4 = idx & 7;
                hreg[i] = *reinterpret_cast<const float4*>(
                    hidden + (size_t)(tok0 + r)*HH + k0 + c4*4);
            }
#pragma unroll
            for (int i = 0; i < 8; i++) {
                int idx = tid + i*256;
                int kk = idx >> 6, c = idx & 63;
                float v = 0.f;
                if (c < TTAG)    v = Wt[(k0+kk)*TTAG + c];
                else if (c < 62) v = Wp[(k0+kk)*TPOS + (c - TTAG)];
                wreg[i] = v;
            }
        }
#pragma unroll
        for (int kk = 0; kk < 32; kk++) {
            float4 bv = *reinterpret_cast<float4*>(&Ws[kk*64 + tx*4]);
#pragma unroll
            for (int i = 0; i < 8; i++) {
                float a = Hs[(ty*8+i)*36 + kk];
                acc[i][0] = fmaf(a, bv.x, acc[i][0]);
                acc[i][1] = fmaf(a, bv.y, acc[i][1]);
                acc[i][2] = fmaf(a, bv.z, acc[i][2]);
                acc[i][3] = fmaf(a, bv.w, acc[i][3]);
            }
        }
        __syncthreads();
    }
#pragma unroll
    for (int i = 0; i < 8; i++) {
        if (tx == 0) e0t[ty*8+i] = acc[i][0] + bt[0];
        if (tx == 4) e0p[ty*8+i] = acc[i][1] + bp[0];
    }
    __syncthreads();
#pragma unroll
    for (int i = 0; i < 8; i++) {
        int rl = ty*8 + i;
        int r = tok0 + rl;
#pragma unroll
        for (int j = 0; j < 4; j++) {
            int c = tx*4 + j;
            if (c < TTAG) {
                float v = acc[i][j] + bt[c];
                g_tag [(size_t)r*TTAG + c] = v;
                g_Etag[(size_t)r*TTAG + c] = __expf(v - e0t[rl]);
            } else if (c < 62) {
                int cp = c - TTAG;
                float v = acc[i][j] + bp[cp];
                g_pos [(size_t)r*TPOS + cp] = v;
                g_Epos[(size_t)r*TPOS + cp] = __expf(v - e0p[rl]);
            }
        }
    }
}

// ============================================================
// CRF: one block per (head,batch). 160 threads:
//   warp 0:  self-contained forward (syncwarp loop, rescale every 8)
//   warps 1-3: Viterbi (2 lanes/col; reads emissions from SMEM ring)
//   warp 4:  emission stager (double-buffered 32-step chunks), then numerator
// bars: id2 = per-step {w1-3} (96); id3 = chunk boundary {w1-4} (128)
// ============================================================
#define CHUNK 32
#define ESTR  46   // padded row stride in staged buffer

struct __align__(16) CrfSmem {
    float a2[2][96];            // duplicated pairs (a_i,a_i)
    float sv[2][48];
    float es[2][CHUNK*ESTR];    // staged raw emissions (viterbi)
    unsigned mword[16];
    float num_sh, den_sh, e0sum;
    unsigned char hist[(SS-1)*MAXT];
    unsigned char path[SS];
};

template<int T>
__device__ __forceinline__ void crf_chain(
    CrfSmem& s,
    const float* __restrict__ stg, const float* __restrict__ trg,
    const float* __restrict__ eng,
    const int* __restrict__ tgt, const int* __restrict__ mask,
    const float* __restrict__ eb, const float* __restrict__ Eb, int b)
{
    const int tid = threadIdx.x;
    const int w = tid >> 5, lane = tid & 31;
    constexpr int SHC = (T + 1) / 2;
    constexpr int BASE_B = (T/2) & ~3;
    constexpr int CA = T - BASE_B;
    constexpr int BIG = 1 << 20;
    constexpr int NCHUNK = SS / CHUNK;   // 16

    // ---- init ----
    if (tid < 16) {
        unsigned bits = 0;
#pragma unroll
        for (int k = 0; k < 32; k++)
            bits |= (mask[b*SS + tid*32 + k] != 0 ? 1u : 0u) << k;
        s.mword[tid] = bits;
    }
    // cooperative stage of chunk 0 (steps 0..31)
    for (int i = tid; i < CHUNK*T; i += 160) {
        int st = i / T, j = i - st*T;
        s.es[0][st*ESTR + j] = eb[st*T + j];
    }
    if (w == 0 && lane < SHC) {
        int j0 = lane, j1 = (lane + SHC < T) ? lane + SHC : lane;
        float r0 = stg[0] + eb[0];
        float a0 = __expf(stg[j0] + eb[j0] - r0);
        float a1 = __expf(stg[j1] + eb[j1] - r0);
        *(unsigned long long*)&s.a2[0][2*j0] = pack2(a0, a0);
        *(unsigned long long*)&s.a2[0][2*j1] = pack2(a1, a1);
    }
    if (w >= 1 && w <= 3) {
        int vl = tid - 32, col = vl >> 1;
        if (col < T && !(vl & 1)) s.sv[0][col] = stg[col] + eb[col];
    }
    __syncthreads();

    if (w == 0) {
        // ============ forward warp: fully self-contained ============
        const bool act = lane < SHC;
        const int j0 = act ? lane : 0;
        const bool j1ok = act && (lane + SHC < T);
        const int j1 = j1ok ? lane + SHC : j0;
        const float wm0 = act ? 1.f : 0.f;
        const float wm1 = j1ok ? 1.f : 0.f;
        unsigned long long tc2[T];
#pragma unroll
        for (int i = 0; i < T; i++)
            tc2[i] = pack2(__expf(trg[i*T + j0]), __expf(trg[i*T + j1]));
        const float ref0 = stg[0] + eb[0];
        float acur0 = __expf(stg[j0] + eb[j0] - ref0);
        float acur1 = __expf(stg[j1] + eb[j1] - ref0);
        float E0n = Eb[T + j0], E1n = Eb[T + j1];
        float Lr = 0.f;

        for (int t = 1; t < SS; t++) {
            const int pb = (t-1) & 1, cb = t & 1;
            unsigned mt = (s.mword[t >> 5] >> (t & 31)) & 1u;
            float E0 = E0n, E1 = E1n;
            if (t + 1 < SS) { E0n = Eb[(size_t)(t+1)*T + j0]; E1n = Eb[(size_t)(t+1)*T + j1]; }

            unsigned long long d[4] = {0ull, 0ull, 0ull, 0ull};
            const float* ap = s.a2[pb];
#pragma unroll
            for (int k = 0; k < T/2; k++) {
                ulonglong2 q = *(const ulonglong2*)(ap + 4*k);
                fma2(d[(2*k) & 3],   q.x, tc2[2*k]);
                fma2(d[(2*k+1) & 3], q.y, tc2[2*k+1]);
            }
            if (T & 1) {
                unsigned long long qa = *(const unsigned long long*)(ap + 2*(T-1));
                fma2(d[(T-1) & 3], qa, tc2[T-1]);
            }
            unsigned long long dd = add2(add2(d[0], d[1]), add2(d[2], d[3]));
            float dot0, dot1; unpack2(dd, dot0, dot1);
            float v0 = mt ? dot0 * E0 : acur0;
            float v1 = mt ? dot1 * E1 : acur1;
            if ((t & 7) == 0) {
                // amortized rescale: uniform factor, exactly compensated in Lr
                float ssum = fmaf(v1, wm1, v0 * wm0);
#pragma unroll
                for (int o = 16; o > 0; o >>= 1)
                    ssum += __shfl_xor_sync(0xffffffffu, ssum, o);
                float iv = 1.f / ssum;
                Lr += __logf(ssum);
                v0 *= iv; v1 *= iv;
            }
            acur0 = v0; acur1 = v1;
            if (act) {
                *(unsigned long long*)&s.a2[cb][2*j0] = pack2(v0, v0);
                *(unsigned long long*)&s.a2[cb][2*j1] = pack2(v1, v1);
            }
            __syncwarp();
        }
        if (lane == 0) {
            float sm = 0.f;
#pragma unroll
            for (int i = 0; i < T; i++) sm += s.a2[1][2*i] * __expf(eng[i]);
            s.den_sh = ref0 + Lr + __logf(sm);   // + e0sum added at combine
        }
    } else if (w == 4) {
        // ============ emission stager, then numerator one-shot ============
        for (int c = 1; c < NCHUNK; c++) {
            const float* src = eb + (size_t)(c*CHUNK)*T;
            float* dst = s.es[c & 1];
            for (int i = lane; i < CHUNK*T; i += 32) {
                int st = i / T, j = i - st*T;
                dst[st*ESTR + j] = src[st*T + j];
            }
            asm volatile("bar.sync 3, 128;" ::: "memory");
        }
        // numerator + masked-e0 sum
        float pacc = 0.f, esum = 0.f; int mxt = 0;
        for (int t = lane; t < SS; t += 32) {
            int tg = tgt[b*SS + t];
            if (t == 0) {
                pacc += stg[tg] + eb[tg];
            } else if (mask[b*SS + t] > 0) {
                int tgp = tgt[b*SS + t - 1];
                pacc += trg[tgp*T + tg] + eb[(size_t)t*T + tg];
                esum += eb[(size_t)t*T];
                mxt = max(mxt, t);
            }
        }
#pragma unroll
        for (int o = 16; o > 0; o >>= 1) {
            pacc += __shfl_xor_sync(0xffffffffu, pacc, o);
            esum += __shfl_xor_sync(0xffffffffu, esum, o);
            mxt = max(mxt, __shfl_xor_sync(0xffffffffu, mxt, o));
        }
        if (lane == 0) {
            s.num_sh = pacc + eng[tgt[b*SS + mxt]];
            s.e0sum = esum;
        }
    } else {
        // ===== viterbi warps (1-3): emissions from SMEM ring, no LDG =====
        const int vl = tid - 32;
        const int col = vl >> 1;
        const bool act = col < T;
        const bool isA = !(vl & 1);
        const int jj = act ? col : 0;
        const int base = isA ? 0 : BASE_B;
        float tc[CA];
#pragma unroll
        for (int k = 0; k < CA; k++) tc[k] = trg[(base + k)*T + jj];
        float svprev = stg[jj] + eb[jj];

        for (int t = 1; t < SS; t++) {
            if ((t & (CHUNK-1)) == 0)
                asm volatile("bar.sync 3, 128;" ::: "memory");   // next chunk staged
            const int pb = (t-1) & 1, cb = t & 1;
            float ev = s.es[(t >> 5) & 1][(t & (CHUNK-1))*ESTR + jj];  // broadcast LDS

            float cand[CA];
            const float* sp = s.sv[pb] + base;
            constexpr int C4 = CA / 4;
#pragma unroll
            for (int k = 0; k < C4; k++) {
                float4 q = *(const float4*)(sp + 4*k);
                cand[4*k+0] = q.x + tc[4*k+0];
                cand[4*k+1] = q.y + tc[4*k+1];
                cand[4*k+2] = q.z + tc[4*k+2];
                cand[4*k+3] = q.w + tc[4*k+3];
            }
#pragma unroll
            for (int r = 4*C4; r < CA; r++) cand[r] = sp[r] + tc[r];

            // value max: 4-accumulator FMNMX trees
            float mx0 = cand[0];
            float mx1 = (CA > 1) ? cand[1] : cand[0];
            float mx2 = (CA > 2) ? cand[2] : cand[0];
            float mx3 = (CA > 3) ? cand[3] : cand[0];
#pragma unroll
            for (int k = 4; k < CA; k++) {
                if ((k & 3) == 0) mx0 = fmaxf(mx0, cand[k]);
                else if ((k & 3) == 1) mx1 = fmaxf(mx1, cand[k]);
                else if ((k & 3) == 2) mx2 = fmaxf(mx2, cand[k]);
                else mx3 = fmaxf(mx3, cand[k]);
            }
            float best = fmaxf(fmaxf(mx0, mx1), fmaxf(mx2, mx3));
            // lowest index: equality bitmask (pred-as-data) + ffs
            unsigned msk = 0u;
#pragma unroll
            for (int k = 0; k < CA; k++)
                msk |= (cand[k] == best) ? (1u << k) : 0u;
            int arg = base + (__ffs(msk) - 1);
            // merge with partner lane (min global index on value ties)
            float bo = __shfl_xor_sync(0xffffffffu, best, 1);
            int   io = __shfl_xor_sync(0xffffffffu, arg, 1);
            float bm = fmaxf(best, bo);
            int ia = (best == bm) ? arg : BIG;
            int ib = (bo == bm) ? io : BIG;
            int argm = min(ia, ib);

            if (isA && act) {
                unsigned mt = (s.mword[t >> 5] >> (t & 31)) & 1u;
                float svnew; int h;
                if (mt) { svnew = bm + ev; h = argm; }
                else    { svnew = svprev;  h = col; }
                s.sv[cb][col] = svnew;
                svprev = svnew;
                s.hist[(t-1)*T + col] = (unsigned char)h;
            }
            asm volatile("bar.sync 2, 96;" ::: "memory");
        }
        // backtrace (warp 1, lane 0)
        if (tid == 32) {
            float bv = -1e30f; int cur = 0;
#pragma unroll
            for (int j = 0; j < T; j++) {
                float c = s.sv[1][j] + eng[j];
                if (c > bv) { bv = c; cur = j; }
            }
            s.path[SS-1] = (unsigned char)cur;
            for (int tt = SS-1; tt >= 1; tt--) {
                cur = s.hist[(tt-1)*T + cur];
                s.path[tt-1] = (unsigned char)cur;
            }
        }
    }
}

__global__ __launch_bounds__(160) void crf_kernel(
    const float* __restrict__ st_t, const float* __restrict__ tr_t, const float* __restrict__ en_t,
    const float* __restrict__ st_p, const float* __restrict__ tr_p, const float* __restrict__ en_p,
    const int* __restrict__ tgt_t, const int* __restrict__ tgt_p,
    const int* __restrict__ mask,
    float* __restrict__ out, int out_size)
{
    __shared__ CrfSmem s;
    const int head = blockIdx.x >> 6;
    const int b    = blockIdx.x & 63;
    float* pred = out + (size_t)head*MM + (size_t)b*SS;
    if (head == 0)
        crf_chain<TTAG>(s, st_t, tr_t, en_t, tgt_t, mask,
                        g_tag  + (size_t)b*SS*TTAG,
                        g_Etag + (size_t)b*SS*TTAG, b);
    else
        crf_chain<TPOS>(s, st_p, tr_p, en_p, tgt_p, mask,
                        g_pos  + (size_t)b*SS*TPOS,
                        g_Epos + (size_t)b*SS*TPOS, b);
    __syncthreads();
    // coalesced path write (warp 0 now free)
    if (threadIdx.x < 32)
        for (int i = threadIdx.x; i < SS; i += 32) pred[i] = (float)s.path[i];
    // fused finalize: last block sums all diffs
    if (threadIdx.x == 0) {
        g_diff[head*BB + b] = s.num_sh - (s.den_sh + s.e0sum);
        __threadfence();
        int old = atomicAdd(&g_cnt, 1);
        if (old == 2*BB - 1) {
            __threadfence();
            float s0 = 0.f, s1 = 0.f;
            for (int i = 0; i < BB; i++) { s0 += g_diff[i]; s1 += g_diff[BB + i]; }
            if (out_size > 2*MM)     out[2*MM]     = -s0 / (float)BB;
            if (out_size > 2*MM + 1) out[2*MM + 1] = -s1 / (float)BB;
            g_cnt = 0;   // reset for next graph replay
        }
    }
}

extern "C" void kernel_launch(void* const* d_in, const int* in_sizes, int n_in,
                              void* d_out, int out_size)
{
    const float* hidden = (const float*)d_in[0];
    const int*   mask   = (const int*)d_in[1];
    const int*   tgt_t  = (const int*)d_in[2];
    const int*   tgt_p  = (const int*)d_in[3];
    const float* Wt     = (const float*)d_in[4];
    const float* bt     = (const float*)d_in[5];
    const float* Wp     = (const float*)d_in[6];
    const float* bp     = (const float*)d_in[7];
    const float* st_t   = (const float*)d_in[8];
    const float* tr_t   = (const float*)d_in[9];
    const float* en_t   = (const float*)d_in[10];
    const float* st_p   = (const float*)d_in[11];
    const float* tr_p   = (const float*)d_in[12];
    const float* en_p   = (const float*)d_in[13];
    float* out = (float*)d_out;

    gemm_kernel<<<MM/128, 256>>>(hidden, Wt, bt, Wp, bp);
    crf_kernel<<<2*BB, 160>>>(st_t, tr_t, en_t, st_p, tr_p, en_p,
                              tgt_t, tgt_p, mask, out, out_size);
}

// round 16
// speedup vs baseline: 1.1374x; 1.1079x over previous
#include <cuda_runtime.h>

#define BB 64
#define SS 512
#define HH 768
#define TTAG 17
#define TPOS 45
#define MM (BB*SS)
#define MAXT 45

// ---- scratch (no allocations allowed) ----
__device__ float g_tag[MM*TTAG];
__device__ float g_pos[MM*TPOS];
__device__ float g_Etag[MM*TTAG];   // exp(e_j - e_0)
__device__ float g_Epos[MM*TPOS];
__device__ float g_diff[2*BB];
__device__ int   g_cnt;             // zero-init; reset by finalizing block

// ============================================================
// GEMM + fused E precompute (validated; ~100us)
// ============================================================
__global__ __launch_bounds__(256, 2) void gemm_kernel(
    const float* __restrict__ hidden,
    const float* __restrict__ Wt, const float* __restrict__ bt,
    const float* __restrict__ Wp, const float* __restrict__ bp)
{
    __shared__ float Hs[128*36];
    __shared__ float Ws[32*64];
    __shared__ float e0t[128], e0p[128];
    const int tid = threadIdx.x;
    const int ty = tid >> 4, tx = tid & 15;
    const int tok0 = blockIdx.x * 128;

    float acc[8][4];
#pragma unroll
    for (int i = 0; i < 8; i++)
#pragma unroll
        for (int j = 0; j < 4; j++) acc[i][j] = 0.f;

    float4 hreg[4];
    float  wreg[8];
    {
#pragma unroll
        for (int i = 0; i < 4; i++) {
            int idx = tid + i*256;
            int r = idx >> 3, c4 = idx & 7;
            hreg[i] = *reinterpret_cast<const float4*>(
                hidden + (size_t)(tok0 + r)*HH + c4*4);
        }
#pragma unroll
        for (int i = 0; i < 8; i++) {
            int idx = tid + i*256;
            int kk = idx >> 6, c = idx & 63;
            float v = 0.f;
            if (c < TTAG)    v = Wt[kk*TTAG + c];
            else if (c < 62) v = Wp[kk*TPOS + (c - TTAG)];
            wreg[i] = v;
        }
    }
    for (int ch = 0; ch < HH/32; ch++) {
#pragma unroll
        for (int i = 0; i < 4; i++) {
            int idx = tid + i*256;
            int r = idx >> 3, c4 = idx & 7;
            *reinterpret_cast<float4*>(&Hs[r*36 + c4*4]) = hreg[i];
        }
#pragma unroll
        for (int i = 0; i < 8; i++) Ws[tid + i*256] = wreg[i];
        __syncthreads();
        if (ch + 1 < HH/32) {
            const int k0 = (ch+1)*32;
#pragma unroll
            for (int i = 0; i < 4; i++) {
                int idx = tid + i*256;
                int r = idx >> 3, c4 = idx & 7;
                hreg[i] = *reinterpret_cast<const float4*>(
                    hidden + (size_t)(tok0 + r)*HH + k0 + c4*4);
            }
#pragma unroll
            for (int i = 0; i < 8; i++) {
                int idx = tid + i*256;
                int kk = idx >> 6, c = idx & 63;
                float v = 0.f;
                if (c < TTAG)    v = Wt[(k0+kk)*TTAG + c];
                else if (c < 62) v = Wp[(k0+kk)*TPOS + (c - TTAG)];
                wreg[i] = v;
            }
        }
#pragma unroll
        for (int kk = 0; kk < 32; kk++) {
            float4 bv = *reinterpret_cast<float4*>(&Ws[kk*64 + tx*4]);
#pragma unroll
            for (int i = 0; i < 8; i++) {
                float a = Hs[(ty*8+i)*36 + kk];
                acc[i][0] = fmaf(a, bv.x, acc[i][0]);
                acc[i][1] = fmaf(a, bv.y, acc[i][1]);
                acc[i][2] = fmaf(a, bv.z, acc[i][2]);
                acc[i][3] = fmaf(a, bv.w, acc[i][3]);
            }
        }
        __syncthreads();
    }
#pragma unroll
    for (int i = 0; i < 8; i++) {
        if (tx == 0) e0t[ty*8+i] = acc[i][0] + bt[0];
        if (tx == 4) e0p[ty*8+i] = acc[i][1] + bp[0];
    }
    __syncthreads();
#pragma unroll
    for (int i = 0; i < 8; i++) {
        int rl = ty*8 + i;
        int r = tok0 + rl;
#pragma unroll
        for (int j = 0; j < 4; j++) {
            int c = tx*4 + j;
            if (c < TTAG) {
                float v = acc[i][j] + bt[c];
                g_tag [(size_t)r*TTAG + c] = v;
                g_Etag[(size_t)r*TTAG + c] = __expf(v - e0t[rl]);
            } else if (c < 62) {
                int cp = c - TTAG;
                float v = acc[i][j] + bp[cp];
                g_pos [(size_t)r*TPOS + cp] = v;
                g_Epos[(size_t)r*TPOS + cp] = __expf(v - e0p[rl]);
            }
        }
    }
}

// ============================================================
// CRF: one block per (head,batch). 160 threads:
//   warps 0 & 4: forward recurrence, ONE column per lane (no spills),
//                coupled by bar.sync 1,64; rescale every 8 steps (lag-1)
//   warps 1-3:   Viterbi (2 lanes/col), bar.sync 2,96
//   warp 3 epilogue: numerator + masked-e0 sum
// ============================================================
struct __align__(16) CrfSmem {
    float a[2][48];        // forward state (plain floats, padded)
    float sv[2][48];
    float part[2][2];      // rescale partials [buf][half]
    unsigned mword[16];
    float num_sh, den_sh, e0sum;
    unsigned char hist[(SS-1)*MAXT];
    unsigned char path[SS];
};

template<int T>
__device__ __forceinline__ void crf_chain(
    CrfSmem& s,
    const float* __restrict__ stg, const float* __restrict__ trg,
    const float* __restrict__ eng,
    const int* __restrict__ tgt, const int* __restrict__ mask,
    const float* __restrict__ eb, const float* __restrict__ Eb, int b)
{
    const int tid = threadIdx.x;
    const int w = tid >> 5, lane = tid & 31;
    constexpr int SHC = (T + 1) / 2;         // columns in warp-0 half
    constexpr int T4 = (T + 3) & ~3;         // padded length for float4 dot
    constexpr int BASE_B = (T/2) & ~3;
    constexpr int CA = T - BASE_B;
    constexpr int BIG = 1 << 20;

    // ---- init ----
    if (tid < 16) {
        unsigned bits = 0;
#pragma unroll
        for (int k = 0; k < 32; k++)
            bits |= (mask[b*SS + tid*32 + k] != 0 ? 1u : 0u) << k;
        s.mword[tid] = bits;
    }
    // zero state pads (both buffers); read by float4 dot, never re-written
    if (tid < 48 - T) { s.a[0][T + tid] = 0.f; s.a[1][T + tid] = 0.f; }

    const float ref0 = stg[0] + eb[0];
    if (w == 0 && lane < SHC)
        s.a[0][lane] = __expf(stg[lane] + eb[lane] - ref0);
    if (w == 4 && SHC + lane < T)
        s.a[0][SHC + lane] = __expf(stg[SHC + lane] + eb[SHC + lane] - ref0);
    if (w >= 1 && w <= 3) {
        int vl = tid - 32, col = vl >> 1;
        if (col < T && !(vl & 1)) s.sv[0][col] = stg[col] + eb[col];
    }
    __syncthreads();

    if (w == 0 || w == 4) {
        // ========== forward warps: one column per lane ==========
        const int half = (w == 4) ? 1 : 0;
        const int jr = half ? (SHC + lane) : lane;
        const bool act = half ? (jr < T) : (lane < SHC);
        const int j = act ? jr : 0;

        float tc[T4];
#pragma unroll
        for (int i = 0; i < T; i++) tc[i] = __expf(trg[i*T + j]);
#pragma unroll
        for (int i = T; i < T4; i++) tc[i] = 0.f;

        float acur = __expf(stg[j] + eb[j] - ref0);
        float Eq1 = Eb[T + j];
        float Eq2 = Eb[2*T + j];
        float pend = 1.f, Lr = 0.f;

        for (int t = 1; t < SS; t++) {
            const int pb = (t-1) & 1, cb = t & 1;
            const unsigned mt = (s.mword[t >> 5] >> (t & 31)) & 1u;
            float E = Eq1; Eq1 = Eq2;
            if (t + 2 < SS) Eq2 = Eb[(size_t)(t+2)*T + j];

            // rescale factor arrives one step after partials were written
            if ((t & 7) == 1 && t > 8) {
                int buf = ((t-1) >> 3) & 1;
                float ssum = s.part[buf][0] + s.part[buf][1];
                pend *= 1.f / ssum;
            }

            float d0 = 0.f, d1 = 0.f, d2 = 0.f, d3 = 0.f;
            const float* ap = s.a[pb];
#pragma unroll
            for (int k = 0; k < T4/4; k++) {
                float4 q = *(const float4*)(ap + 4*k);
                d0 = fmaf(q.x, tc[4*k+0], d0);
                d1 = fmaf(q.y, tc[4*k+1], d1);
                d2 = fmaf(q.z, tc[4*k+2], d2);
                d3 = fmaf(q.w, tc[4*k+3], d3);
            }
            float dot = (d0 + d1) + (d2 + d3);
            float v;
            if (mt) {
                v = dot * E * pend;
                if (pend != 1.f) {
                    if (half == 0 && lane == 0) Lr -= __logf(pend);  // exact comp
                    pend = 1.f;
                }
            } else {
                v = acur;
            }
            acur = v;
            if (act) s.a[cb][j] = v;

            if ((t & 7) == 0) {      // publish rescale partial (consumed at t+1)
                float p = act ? v : 0.f;
#pragma unroll
                for (int o = 16; o > 0; o >>= 1)
                    p += __shfl_xor_sync(0xffffffffu, p, o);
                if (lane == 0) s.part[(t >> 3) & 1][half] = p;
            }
            asm volatile("bar.sync 1, 64;" ::: "memory");
        }
        if (half == 0 && lane == 0) {
            float sm = 0.f;
#pragma unroll
            for (int i = 0; i < T; i++) sm += s.a[1][i] * __expf(eng[i]);
            s.den_sh = ref0 + Lr + __logf(sm);   // + e0sum added at combine
        }
    } else {
        // ===== viterbi warps (1-3): FMNMX-tree max + ffs index =====
        const int vl = tid - 32;
        const int col = vl >> 1;
        const bool act = col < T;
        const bool isA = !(vl & 1);
        const int jj = act ? col : 0;
        const int base = isA ? 0 : BASE_B;
        float tc[CA];
#pragma unroll
        for (int k = 0; k < CA; k++) tc[k] = trg[(base + k)*T + jj];
        float svprev = stg[jj] + eb[jj];
        float evq1 = eb[T + jj];
        float evq2 = eb[2*T + jj];

        for (int t = 1; t < SS; t++) {
            const int pb = (t-1) & 1, cb = t & 1;
            float ev = evq1; evq1 = evq2;                // distance-2 prefetch
            if (t + 2 < SS) evq2 = eb[(size_t)(t+2)*T + jj];

            float cand[CA];
            const float* sp = s.sv[pb] + base;
            constexpr int C4 = CA / 4;
#pragma unroll
            for (int k = 0; k < C4; k++) {
                float4 q = *(const float4*)(sp + 4*k);
                cand[4*k+0] = q.x + tc[4*k+0];
                cand[4*k+1] = q.y + tc[4*k+1];
                cand[4*k+2] = q.z + tc[4*k+2];
                cand[4*k+3] = q.w + tc[4*k+3];
            }
#pragma unroll
            for (int r = 4*C4; r < CA; r++) cand[r] = sp[r] + tc[r];

            float mx0 = cand[0];
            float mx1 = (CA > 1) ? cand[1] : cand[0];
            float mx2 = (CA > 2) ? cand[2] : cand[0];
            float mx3 = (CA > 3) ? cand[3] : cand[0];
#pragma unroll
            for (int k = 4; k < CA; k++) {
                if ((k & 3) == 0) mx0 = fmaxf(mx0, cand[k]);
                else if ((k & 3) == 1) mx1 = fmaxf(mx1, cand[k]);
                else if ((k & 3) == 2) mx2 = fmaxf(mx2, cand[k]);
                else mx3 = fmaxf(mx3, cand[k]);
            }
            float best = fmaxf(fmaxf(mx0, mx1), fmaxf(mx2, mx3));
            unsigned msk = 0u;
#pragma unroll
            for (int k = 0; k < CA; k++)
                msk |= (cand[k] == best) ? (1u << k) : 0u;
            int arg = base + (__ffs(msk) - 1);
            float bo = __shfl_xor_sync(0xffffffffu, best, 1);
            int   io = __shfl_xor_sync(0xffffffffu, arg, 1);
            float bm = fmaxf(best, bo);
            int ia = (best == bm) ? arg : BIG;
            int ib = (bo == bm) ? io : BIG;
            int argm = min(ia, ib);

            if (isA && act) {
                unsigned mt = (s.mword[t >> 5] >> (t & 31)) & 1u;
                float svnew; int h;
                if (mt) { svnew = bm + ev; h = argm; }
                else    { svnew = svprev;  h = col; }
                s.sv[cb][col] = svnew;
                svprev = svnew;
                s.hist[(t-1)*T + col] = (unsigned char)h;
            }
            asm volatile("bar.sync 2, 96;" ::: "memory");
        }
        // backtrace (warp 1, lane 0)
        if (tid == 32) {
            float bv = -1e30f; int cur = 0;
#pragma unroll
            for (int j = 0; j < T; j++) {
                float c = s.sv[1][j] + eng[j];
                if (c > bv) { bv = c; cur = j; }
            }
            s.path[SS-1] = (unsigned char)cur;
            for (int tt = SS-1; tt >= 1; tt--) {
                cur = s.hist[(tt-1)*T + cur];
                s.path[tt-1] = (unsigned char)cur;
            }
        }
        // numerator + masked-e0 sum (warp 3, after its loop)
        if (w == 3) {
            float pacc = 0.f, esum = 0.f; int mxt = 0;
            for (int t = lane; t < SS; t += 32) {
                int tg = tgt[b*SS + t];
                if (t == 0) {
                    pacc += stg[tg] + eb[tg];
                } else if (mask[b*SS + t] > 0) {
                    int tgp = tgt[b*SS + t - 1];
                    pacc += trg[tgp*T + tg] + eb[(size_t)t*T + tg];
                    esum += eb[(size_t)t*T];
                    mxt = max(mxt, t);
                }
            }
#pragma unroll
            for (int o = 16; o > 0; o >>= 1) {
                pacc += __shfl_xor_sync(0xffffffffu, pacc, o);
                esum += __shfl_xor_sync(0xffffffffu, esum, o);
                mxt = max(mxt, __shfl_xor_sync(0xffffffffu, mxt, o));
            }
            if (lane == 0) {
                s.num_sh = pacc + eng[tgt[b*SS + mxt]];
                s.e0sum = esum;
            }
        }
    }
}

__global__ __launch_bounds__(160) void crf_kernel(
    const float* __restrict__ st_t, const float* __restrict__ tr_t, const float* __restrict__ en_t,
    const float* __restrict__ st_p, const float* __restrict__ tr_p, const float* __restrict__ en_p,
    const int* __restrict__ tgt_t, const int* __restrict__ tgt_p,
    const int* __restrict__ mask,
    float* __restrict__ out, int out_size)
{
    __shared__ CrfSmem s;
    const int head = blockIdx.x >> 6;
    const int b    = blockIdx.x & 63;
    float* pred = out + (size_t)head*MM + (size_t)b*SS;
    if (head == 0)
        crf_chain<TTAG>(s, st_t, tr_t, en_t, tgt_t, mask,
                        g_tag  + (size_t)b*SS*TTAG,
                        g_Etag + (size_t)b*SS*TTAG, b);
    else
        crf_chain<TPOS>(s, st_p, tr_p, en_p, tgt_p, mask,
                        g_pos  + (size_t)b*SS*TPOS,
                        g_Epos + (size_t)b*SS*TPOS, b);
    __syncthreads();
    // coalesced path write
    if (threadIdx.x < 32)
        for (int i = threadIdx.x; i < SS; i += 32) pred[i] = (float)s.path[i];
    // fused finalize: last block sums all diffs
    if (threadIdx.x == 0) {
        g_diff[head*BB + b] = s.num_sh - (s.den_sh + s.e0sum);
        __threadfence();
        int old = atomicAdd(&g_cnt, 1);
        if (old == 2*BB - 1) {
            __threadfence();
            float s0 = 0.f, s1 = 0.f;
            for (int i = 0; i < BB; i++) { s0 += g_diff[i]; s1 += g_diff[BB + i]; }
            if (out_size > 2*MM)     out[2*MM]     = -s0 / (float)BB;
            if (out_size > 2*MM + 1) out[2*MM + 1] = -s1 / (float)BB;
            g_cnt = 0;   // reset for next graph replay
        }
    }
}

extern "C" void kernel_launch(void* const* d_in, const int* in_sizes, int n_in,
                              void* d_out, int out_size)
{
    const float* hidden = (const float*)d_in[0];
    const int*   mask   = (const int*)d_in[1];
    const int*   tgt_t  = (const int*)d_in[2];
    const int*   tgt_p  = (const int*)d_in[3];
    const float* Wt     = (const float*)d_in[4];
    const float* bt     = (const float*)d_in[5];
    const float* Wp     = (const float*)d_in[6];
    const float* bp     = (const float*)d_in[7];
    const float* st_t   = (const float*)d_in[8];
    const float* tr_t   = (const float*)d_in[9];
    const float* en_t   = (const float*)d_in[10];
    const float* st_p   = (const float*)d_in[11];
    const float* tr_p   = (const float*)d_in[12];
    const float* en_p   = (const float*)d_in[13];
    float* out = (float*)d_out;

    gemm_kernel<<<MM/128, 256>>>(hidden, Wt, bt, Wp, bp);
    crf_kernel<<<2*BB, 160>>>(st_t, tr_t, en_t, st_p, tr_p, en_p,
                              tgt_t, tgt_p, mask, out, out_size);
}